// round 1
// baseline (speedup 1.0000x reference)
#include <cuda_runtime.h>
#include <cuda_bf16.h>
#include <math.h>
#include <stdint.h>

// Problem constants
#define B_   4
#define S_   1024
#define T_   4096          // B*S
#define H_   32
#define D_   80
#define HID_ 2560          // H*D
#define QKV_N 7680         // 3*HID
#define ROT_ 32
#define HALF_ 16
#define SCALE_ 0.11180339887498948f   // 80^-0.5

// ---------------------------------------------------------------------------
// Scratch (device globals; no runtime allocation allowed)
// ---------------------------------------------------------------------------
__device__ float g_qkv[(size_t)T_ * QKV_N];   // 125.8 MB
__device__ float g_attn[(size_t)T_ * HID_];   // 41.9 MB

// ---------------------------------------------------------------------------
// Generic GEMM: C[M,N] = A[M,K] @ W[N,K]^T + bias[N]
// 128x128 tile, BK=16, 256 threads, 8x8 register blocking.
// ---------------------------------------------------------------------------
#define GT 128
#define GK 16

__global__ __launch_bounds__(256) void gemm_nt_bias(
    const float* __restrict__ A, const float* __restrict__ W,
    const float* __restrict__ bias, float* __restrict__ C,
    int M, int N, int K)
{
    __shared__ float As[GK][GT];
    __shared__ float Ws[GK][GT];

    const int tid = threadIdx.x;
    const int tx = tid & 15;
    const int ty = tid >> 4;
    const int m0 = blockIdx.y * GT;
    const int n0 = blockIdx.x * GT;

    float acc[8][8];
#pragma unroll
    for (int i = 0; i < 8; i++)
#pragma unroll
        for (int j = 0; j < 8; j++) acc[i][j] = 0.0f;

    for (int kt = 0; kt < K; kt += GK) {
        // Load A tile (128 rows x 16 k) -> As[k][m], transposed
#pragma unroll
        for (int u = 0; u < 2; u++) {
            int idx = tid + u * 256;          // 0..511
            int row = idx >> 2;               // 0..127
            int k4  = idx & 3;                // 0..3 (float4 within 16 k's)
            float4 v = *(const float4*)(A + (size_t)(m0 + row) * K + kt + k4 * 4);
            As[k4 * 4 + 0][row] = v.x;
            As[k4 * 4 + 1][row] = v.y;
            As[k4 * 4 + 2][row] = v.z;
            As[k4 * 4 + 3][row] = v.w;
        }
        // Load W tile (128 rows x 16 k) -> Ws[k][n], transposed
#pragma unroll
        for (int u = 0; u < 2; u++) {
            int idx = tid + u * 256;
            int row = idx >> 2;
            int k4  = idx & 3;
            float4 v = *(const float4*)(W + (size_t)(n0 + row) * K + kt + k4 * 4);
            Ws[k4 * 4 + 0][row] = v.x;
            Ws[k4 * 4 + 1][row] = v.y;
            Ws[k4 * 4 + 2][row] = v.z;
            Ws[k4 * 4 + 3][row] = v.w;
        }
        __syncthreads();

#pragma unroll
        for (int k = 0; k < GK; k++) {
            float a[8], b[8];
            *(float4*)(a)     = *(const float4*)&As[k][ty * 8];
            *(float4*)(a + 4) = *(const float4*)&As[k][ty * 8 + 4];
            *(float4*)(b)     = *(const float4*)&Ws[k][tx * 8];
            *(float4*)(b + 4) = *(const float4*)&Ws[k][tx * 8 + 4];
#pragma unroll
            for (int i = 0; i < 8; i++)
#pragma unroll
                for (int j = 0; j < 8; j++)
                    acc[i][j] = fmaf(a[i], b[j], acc[i][j]);
        }
        __syncthreads();
    }

    // Epilogue: add bias, store
    float bb[8];
    *(float4*)(bb)     = *(const float4*)(bias + n0 + tx * 8);
    *(float4*)(bb + 4) = *(const float4*)(bias + n0 + tx * 8 + 4);
#pragma unroll
    for (int i = 0; i < 8; i++) {
        float4 o0, o1;
        o0.x = acc[i][0] + bb[0]; o0.y = acc[i][1] + bb[1];
        o0.z = acc[i][2] + bb[2]; o0.w = acc[i][3] + bb[3];
        o1.x = acc[i][4] + bb[4]; o1.y = acc[i][5] + bb[5];
        o1.z = acc[i][6] + bb[6]; o1.w = acc[i][7] + bb[7];
        float* cp = C + (size_t)(m0 + ty * 8 + i) * N + n0 + tx * 8;
        *(float4*)(cp)     = o0;
        *(float4*)(cp + 4) = o1;
    }
}

// ---------------------------------------------------------------------------
// Partial rotary on q and k halves of qkv scratch, in place.
// idx = which*(T*H*HALF) + t*(H*HALF) + h*HALF + i
// ---------------------------------------------------------------------------
__global__ __launch_bounds__(256) void rope_kernel(
    float* __restrict__ qkv, const float* __restrict__ cosp,
    const float* __restrict__ sinp)
{
    int idx = blockIdx.x * blockDim.x + threadIdx.x;   // 0 .. 2*T*H*HALF-1
    int i = idx & (HALF_ - 1);
    int h = (idx >> 4) & (H_ - 1);
    int t = (idx >> 9) & (T_ - 1);
    int which = idx >> 21;                              // 0 = q, 1 = k
    float* base = qkv + (size_t)t * QKV_N + which * HID_ + h * D_;
    float c = cosp[t * HALF_ + i];
    float s = sinp[t * HALF_ + i];
    float x1 = base[i];
    float x2 = base[i + HALF_];
    base[i]         = x1 * c - x2 * s;
    base[i + HALF_] = x2 * c + x1 * s;
}

// ---------------------------------------------------------------------------
// Causal flash attention. grid = (S/64, B*H), 256 threads.
// Thread (ty,tx): q-rows r = ty*4+i (i<4); k-cols j = tx + 16*jj (jj<4);
// out cols c = tx + 16*cc (cc<5).
// ---------------------------------------------------------------------------
#define BQ 64
#define BKV 64
#define PQ 84                      // padded pitch for Q/K tiles (bank-conflict-free)
#define ATTN_SMEM_FLOATS (BQ*PQ + BKV*PQ + BKV*D_ + BQ*BKV)
#define ATTN_SMEM_BYTES  (ATTN_SMEM_FLOATS * 4)

__global__ __launch_bounds__(256) void attn_kernel(
    const float* __restrict__ qkv, float* __restrict__ outp)
{
    extern __shared__ float sm[];
    float* Qs = sm;                     // [BQ][PQ]
    float* Ks = Qs + BQ * PQ;           // [BKV][PQ]
    float* Vs = Ks + BKV * PQ;          // [BKV][D_]
    float* Ps = Vs + BKV * D_;          // [BQ][BKV]

    const int bh = blockIdx.y;
    const int b  = bh >> 5;
    const int h  = bh & 31;
    const int qt = blockIdx.x;
    const int q0 = qt * BQ;
    const int tid = threadIdx.x;
    const int tx = tid & 15;
    const int ty = tid >> 4;

    const float* Qg = qkv + (size_t)(b * S_) * QKV_N + h * D_;
    const float* Kg = Qg + HID_;
    const float* Vg = Qg + 2 * HID_;

    // Load Q tile (64 rows x 80) -> Qs, pitch 84
    for (int u = tid; u < BQ * 20; u += 256) {
        int r = u / 20, c4 = u % 20;
        *(float4*)&Qs[r * PQ + c4 * 4] =
            *(const float4*)(Qg + (size_t)(q0 + r) * QKV_N + c4 * 4);
    }

    float m_i[4], l_i[4], acc[4][5];
#pragma unroll
    for (int i = 0; i < 4; i++) {
        m_i[i] = -1e30f;
        l_i[i] = 0.0f;
#pragma unroll
        for (int cc = 0; cc < 5; cc++) acc[i][cc] = 0.0f;
    }

    for (int jt = 0; jt <= qt; jt++) {
        // Load K,V tiles
        for (int u = tid; u < BKV * 20; u += 256) {
            int r = u / 20, c4 = u % 20;
            *(float4*)&Ks[r * PQ  + c4 * 4] =
                *(const float4*)(Kg + (size_t)(jt * BKV + r) * QKV_N + c4 * 4);
            *(float4*)&Vs[r * D_ + c4 * 4] =
                *(const float4*)(Vg + (size_t)(jt * BKV + r) * QKV_N + c4 * 4);
        }
        __syncthreads();

        // Scores s[i][jj] = Q[r] . K[j]
        float s[4][4];
#pragma unroll
        for (int i = 0; i < 4; i++)
#pragma unroll
            for (int jj = 0; jj < 4; jj++) s[i][jj] = 0.0f;

        for (int d = 0; d < D_; d += 4) {
            float4 qv[4], kv[4];
#pragma unroll
            for (int i = 0; i < 4; i++)
                qv[i] = *(const float4*)&Qs[(ty * 4 + i) * PQ + d];
#pragma unroll
            for (int jj = 0; jj < 4; jj++)
                kv[jj] = *(const float4*)&Ks[(tx + 16 * jj) * PQ + d];
#pragma unroll
            for (int i = 0; i < 4; i++)
#pragma unroll
                for (int jj = 0; jj < 4; jj++) {
                    s[i][jj] = fmaf(qv[i].x, kv[jj].x, s[i][jj]);
                    s[i][jj] = fmaf(qv[i].y, kv[jj].y, s[i][jj]);
                    s[i][jj] = fmaf(qv[i].z, kv[jj].z, s[i][jj]);
                    s[i][jj] = fmaf(qv[i].w, kv[jj].w, s[i][jj]);
                }
        }

        // Scale + causal mask (only diagonal tile can mask)
#pragma unroll
        for (int i = 0; i < 4; i++) {
            int qg = q0 + ty * 4 + i;
#pragma unroll
            for (int jj = 0; jj < 4; jj++) {
                int jg = jt * BKV + tx + 16 * jj;
                s[i][jj] = (jg > qg) ? -1e30f : s[i][jj] * SCALE_;
            }
        }

        // Online softmax
#pragma unroll
        for (int i = 0; i < 4; i++) {
            float mx = fmaxf(fmaxf(s[i][0], s[i][1]), fmaxf(s[i][2], s[i][3]));
#pragma unroll
            for (int o = 8; o >= 1; o >>= 1)
                mx = fmaxf(mx, __shfl_xor_sync(0xffffffffu, mx, o));
            float mnew = fmaxf(m_i[i], mx);
            float alpha = __expf(m_i[i] - mnew);
            float rsum = 0.0f;
#pragma unroll
            for (int jj = 0; jj < 4; jj++) {
                float p = __expf(s[i][jj] - mnew);
                rsum += p;
                Ps[(ty * 4 + i) * BKV + tx + 16 * jj] = p;
            }
#pragma unroll
            for (int o = 8; o >= 1; o >>= 1)
                rsum += __shfl_xor_sync(0xffffffffu, rsum, o);
            l_i[i] = l_i[i] * alpha + rsum;
            m_i[i] = mnew;
#pragma unroll
            for (int cc = 0; cc < 5; cc++) acc[i][cc] *= alpha;
        }
        __syncthreads();

        // O += P @ V
        for (int j = 0; j < BKV; j += 4) {
            float4 pv[4];
#pragma unroll
            for (int i = 0; i < 4; i++)
                pv[i] = *(const float4*)&Ps[(ty * 4 + i) * BKV + j];
#pragma unroll
            for (int jj2 = 0; jj2 < 4; jj2++) {
                float vv[5];
#pragma unroll
                for (int cc = 0; cc < 5; cc++)
                    vv[cc] = Vs[(j + jj2) * D_ + tx + 16 * cc];
#pragma unroll
                for (int i = 0; i < 4; i++) {
                    float p = (jj2 == 0) ? pv[i].x : (jj2 == 1) ? pv[i].y
                             : (jj2 == 2) ? pv[i].z : pv[i].w;
#pragma unroll
                    for (int cc = 0; cc < 5; cc++)
                        acc[i][cc] = fmaf(p, vv[cc], acc[i][cc]);
                }
            }
        }
        __syncthreads();
    }

    // Epilogue
#pragma unroll
    for (int i = 0; i < 4; i++) {
        float inv = 1.0f / l_i[i];
        float* op = outp + (size_t)(b * S_ + q0 + ty * 4 + i) * HID_ + h * D_;
#pragma unroll
        for (int cc = 0; cc < 5; cc++)
            op[tx + 16 * cc] = acc[i][cc] * inv;
    }
}

// ---------------------------------------------------------------------------
// kernel_launch
// ---------------------------------------------------------------------------
extern "C" void kernel_launch(void* const* d_in, const int* in_sizes, int n_in,
                              void* d_out, int out_size)
{
    const float* hidden  = (const float*)d_in[0];
    const float* cosp    = (const float*)d_in[1];
    const float* sinp    = (const float*)d_in[2];
    const float* w_qkv   = (const float*)d_in[3];
    const float* b_qkv   = (const float*)d_in[4];
    const float* w_dense = (const float*)d_in[5];
    const float* b_dense = (const float*)d_in[6];
    float* outp = (float*)d_out;

    float* qkv = nullptr;
    float* attn = nullptr;
    cudaGetSymbolAddress((void**)&qkv, g_qkv);
    cudaGetSymbolAddress((void**)&attn, g_attn);

    // 1) QKV GEMM + bias
    {
        dim3 grid(QKV_N / GT, T_ / GT);
        gemm_nt_bias<<<grid, 256>>>(hidden, w_qkv, b_qkv, qkv, T_, QKV_N, HID_);
    }

    // 2) Partial RoPE on q and k (in place)
    {
        int total = 2 * T_ * H_ * HALF_;           // 4,194,304
        rope_kernel<<<total / 256, 256>>>(qkv, cosp, sinp);
    }

    // 3) Causal flash attention
    {
        cudaFuncSetAttribute(attn_kernel,
                             cudaFuncAttributeMaxDynamicSharedMemorySize,
                             ATTN_SMEM_BYTES);
        dim3 grid(S_ / BQ, B_ * H_);
        attn_kernel<<<grid, 256, ATTN_SMEM_BYTES>>>(qkv, attn);
    }

    // 4) Dense GEMM + bias
    {
        dim3 grid(HID_ / GT, T_ / GT);
        gemm_nt_bias<<<grid, 256>>>(attn, w_dense, b_dense, outp, T_, HID_, HID_);
    }
}

// round 5
// speedup vs baseline: 2.4781x; 2.4781x over previous
#include <cuda_runtime.h>
#include <cuda_bf16.h>
#include <math.h>
#include <stdint.h>

// Problem constants
#define B_   4
#define S_   1024
#define T_   4096
#define H_   32
#define D_   80
#define HID_ 2560
#define QKV_N 7680
#define HALF_ 16
#define SCALE_ 0.11180339887498948f

// ---------------------------------------------------------------------------
// Scratch (device globals)
// ---------------------------------------------------------------------------
__device__ float g_qkv [(size_t)T_ * QKV_N];
__device__ float g_attn[(size_t)T_ * HID_];
__device__ float g_hidT[(size_t)T_ * HID_];
__device__ float g_wqkvT[(size_t)QKV_N * HID_];
__device__ float g_wdT [(size_t)HID_ * HID_];

// ---------------------------------------------------------------------------
// Helpers
// ---------------------------------------------------------------------------
__device__ __forceinline__ float tf32r(float x) {
    uint32_t r;
    asm("cvt.rna.tf32.f32 %0, %1;" : "=r"(r) : "f"(x));
    return __uint_as_float(r);
}

#define CP_ASYNC16(dst, src) \
    asm volatile("cp.async.cg.shared.global [%0], [%1], 16;" :: "r"(dst), "l"(src) : "memory")
#define CP_COMMIT() asm volatile("cp.async.commit_group;" ::: "memory")
#define CP_WAIT0()  asm volatile("cp.async.wait_group 0;" ::: "memory")
#define CP_WAIT1()  asm volatile("cp.async.wait_group 1;" ::: "memory")

#define MMA_TF32(d, a, b) \
    asm volatile("mma.sync.aligned.m16n8k8.row.col.f32.tf32.tf32.f32 " \
        "{%0,%1,%2,%3}, {%4,%5,%6,%7}, {%8,%9}, {%0,%1,%2,%3};" \
        : "+f"((d)[0]), "+f"((d)[1]), "+f"((d)[2]), "+f"((d)[3]) \
        : "r"((a)[0]), "r"((a)[1]), "r"((a)[2]), "r"((a)[3]), \
          "r"((b)[0]), "r"((b)[1]))

__device__ __forceinline__ uint32_t smem_u32(const void* p) {
    uint32_t a;
    asm("{ .reg .u64 t; cvta.to.shared.u64 t, %1; cvt.u32.u64 %0, t; }"
        : "=r"(a) : "l"(p));
    return a;
}

// ---------------------------------------------------------------------------
// tf32 mma.sync GEMM: C[M,N] = A[M,K] @ W[N,K]^T + bias[N]
// CTA tile 128x128, BK=16, 8 warps, warp tile 64(M)x32(N) = 4x4 m16n8k8 frags.
// Double-buffered cp.async. smem pitch 20 floats (bank-conflict-free frags).
// ---------------------------------------------------------------------------
#define GM 128
#define GN 128
#define GKC 16
#define PITCH 20
#define STG (128 * PITCH)      // floats per stage per operand

__global__ __launch_bounds__(256, 2) void mma_gemm(
    const float* __restrict__ A, const float* __restrict__ W,
    const float* __restrict__ bias, float* __restrict__ C,
    int M, int N, int K)
{
    __shared__ float As[2][STG];
    __shared__ float Bs[2][STG];

    const int tid  = threadIdx.x;
    const int wid  = tid >> 5;
    const int lane = tid & 31;
    const int gid  = lane >> 2;       // 0..7
    const int tig  = lane & 3;        // 0..3
    const int wm   = wid >> 2;        // 0..1 -> M offset 64*wm
    const int wn   = wid & 3;         // 0..3 -> N offset 32*wn
    const int m0 = blockIdx.y * GM;
    const int n0 = blockIdx.x * GN;
    const int nk = K / GKC;

    const uint32_t sa = smem_u32(&As[0][0]);
    const uint32_t sbb = smem_u32(&Bs[0][0]);

    // Per-thread cp.async mapping: 2 float4 chunks per operand per stage.
    const float* srcA[2]; const float* srcB[2]; uint32_t dOff[2];
#pragma unroll
    for (int u = 0; u < 2; u++) {
        int idx = tid + u * 256;      // 0..511
        int row = idx >> 2;           // 0..127
        int kc  = idx & 3;            // float4 index in 16 k's
        srcA[u] = A + (size_t)(m0 + row) * K + kc * 4;
        srcB[u] = W + (size_t)(n0 + row) * K + kc * 4;
        dOff[u] = (uint32_t)(row * PITCH + kc * 4) * 4;   // bytes (16B aligned)
    }

    float acc[4][4][4];
#pragma unroll
    for (int mt = 0; mt < 4; mt++)
#pragma unroll
        for (int nt = 0; nt < 4; nt++)
#pragma unroll
            for (int r = 0; r < 4; r++) acc[mt][nt][r] = 0.0f;

    // Prologue: stage 0
#pragma unroll
    for (int u = 0; u < 2; u++) {
        CP_ASYNC16(sa  + dOff[u], srcA[u]);
        CP_ASYNC16(sbb + dOff[u], srcB[u]);
    }
    CP_COMMIT();

    for (int i = 0; i < nk; i++) {
        const int s = i & 1;
        if (i + 1 < nk) {
            const int s2 = (i + 1) & 1;
            const int kt = (i + 1) * GKC;
            const uint32_t ab = sa  + s2 * (STG * 4);
            const uint32_t bb = sbb + s2 * (STG * 4);
#pragma unroll
            for (int u = 0; u < 2; u++) {
                CP_ASYNC16(ab + dOff[u], srcA[u] + kt);
                CP_ASYNC16(bb + dOff[u], srcB[u] + kt);
            }
            CP_COMMIT();
            CP_WAIT1();
        } else {
            CP_WAIT0();
        }
        __syncthreads();

        const float* as = As[s];
        const float* bs = Bs[s];
#pragma unroll
        for (int ks = 0; ks < 2; ks++) {
            const int k0 = ks * 8;
            uint32_t af[4][4], bf[4][2];
#pragma unroll
            for (int mt = 0; mt < 4; mt++) {
                int r = wm * 64 + mt * 16 + gid;
                af[mt][0] = __float_as_uint(as[r * PITCH + k0 + tig]);
                af[mt][1] = __float_as_uint(as[(r + 8) * PITCH + k0 + tig]);
                af[mt][2] = __float_as_uint(as[r * PITCH + k0 + tig + 4]);
                af[mt][3] = __float_as_uint(as[(r + 8) * PITCH + k0 + tig + 4]);
            }
#pragma unroll
            for (int nt = 0; nt < 4; nt++) {
                int c = wn * 32 + nt * 8 + gid;
                bf[nt][0] = __float_as_uint(bs[c * PITCH + k0 + tig]);
                bf[nt][1] = __float_as_uint(bs[c * PITCH + k0 + tig + 4]);
            }
#pragma unroll
            for (int mt = 0; mt < 4; mt++)
#pragma unroll
                for (int nt = 0; nt < 4; nt++)
                    MMA_TF32(acc[mt][nt], af[mt], bf[nt]);
        }
        __syncthreads();
    }

    // Epilogue: bias + store. c0,c1 -> row gid, cols 2*tig,2*tig+1; c2,c3 -> row gid+8.
#pragma unroll
    for (int mt = 0; mt < 4; mt++) {
        int r = m0 + wm * 64 + mt * 16 + gid;
#pragma unroll
        for (int nt = 0; nt < 4; nt++) {
            int c = n0 + wn * 32 + nt * 8 + tig * 2;
            float b0 = bias[c], b1 = bias[c + 1];
            float2 v0 = make_float2(acc[mt][nt][0] + b0, acc[mt][nt][1] + b1);
            float2 v1 = make_float2(acc[mt][nt][2] + b0, acc[mt][nt][3] + b1);
            *(float2*)(C + (size_t)r * N + c)       = v0;
            *(float2*)(C + (size_t)(r + 8) * N + c) = v1;
        }
    }
}

// ---------------------------------------------------------------------------
// tf32 round (RNA) elementwise convert
// ---------------------------------------------------------------------------
__global__ __launch_bounds__(256) void cvt_tf32_kernel(
    const float4* __restrict__ in, float4* __restrict__ out, int n4)
{
    int i = blockIdx.x * 256 + threadIdx.x;
    if (i >= n4) return;
    float4 v = in[i];
    v.x = tf32r(v.x); v.y = tf32r(v.y); v.z = tf32r(v.z); v.w = tf32r(v.w);
    out[i] = v;
}

// ---------------------------------------------------------------------------
// Partial rotary (in place on q,k of qkv)
// ---------------------------------------------------------------------------
__global__ __launch_bounds__(256) void rope_kernel(
    float* __restrict__ qkv, const float* __restrict__ cosp,
    const float* __restrict__ sinp)
{
    int idx = blockIdx.x * blockDim.x + threadIdx.x;
    int i = idx & (HALF_ - 1);
    int h = (idx >> 4) & (H_ - 1);
    int t = (idx >> 9) & (T_ - 1);
    int which = idx >> 21;
    float* base = qkv + (size_t)t * QKV_N + which * HID_ + h * D_;
    float c = cosp[t * HALF_ + i];
    float s = sinp[t * HALF_ + i];
    float x1 = base[i];
    float x2 = base[i + HALF_];
    base[i]         = x1 * c - x2 * s;
    base[i + HALF_] = x2 * c + x1 * s;
}

// ---------------------------------------------------------------------------
// Causal flash attention (fp32 SIMT), epilogue rounds to tf32 for dense GEMM.
// ---------------------------------------------------------------------------
#define BQ 64
#define BKV 64
#define PQ 84
#define ATTN_SMEM_FLOATS (BQ*PQ + BKV*PQ + BKV*D_ + BQ*BKV)
#define ATTN_SMEM_BYTES  (ATTN_SMEM_FLOATS * 4)

__global__ __launch_bounds__(256) void attn_kernel(
    const float* __restrict__ qkv, float* __restrict__ outp)
{
    extern __shared__ float sm[];
    float* Qs = sm;
    float* Ks = Qs + BQ * PQ;
    float* Vs = Ks + BKV * PQ;
    float* Ps = Vs + BKV * D_;

    const int bh = blockIdx.y;
    const int b  = bh >> 5;
    const int h  = bh & 31;
    const int qt = blockIdx.x;
    const int q0 = qt * BQ;
    const int tid = threadIdx.x;
    const int tx = tid & 15;
    const int ty = tid >> 4;

    const float* Qg = qkv + (size_t)(b * S_) * QKV_N + h * D_;
    const float* Kg = Qg + HID_;
    const float* Vg = Qg + 2 * HID_;

    for (int u = tid; u < BQ * 20; u += 256) {
        int r = u / 20, c4 = u % 20;
        *(float4*)&Qs[r * PQ + c4 * 4] =
            *(const float4*)(Qg + (size_t)(q0 + r) * QKV_N + c4 * 4);
    }

    float m_i[4], l_i[4], acc[4][5];
#pragma unroll
    for (int i = 0; i < 4; i++) {
        m_i[i] = -1e30f;
        l_i[i] = 0.0f;
#pragma unroll
        for (int cc = 0; cc < 5; cc++) acc[i][cc] = 0.0f;
    }

    for (int jt = 0; jt <= qt; jt++) {
        for (int u = tid; u < BKV * 20; u += 256) {
            int r = u / 20, c4 = u % 20;
            *(float4*)&Ks[r * PQ  + c4 * 4] =
                *(const float4*)(Kg + (size_t)(jt * BKV + r) * QKV_N + c4 * 4);
            *(float4*)&Vs[r * D_ + c4 * 4] =
                *(const float4*)(Vg + (size_t)(jt * BKV + r) * QKV_N + c4 * 4);
        }
        __syncthreads();

        float s[4][4];
#pragma unroll
        for (int i = 0; i < 4; i++)
#pragma unroll
            for (int jj = 0; jj < 4; jj++) s[i][jj] = 0.0f;

        for (int d = 0; d < D_; d += 4) {
            float4 qv[4], kv[4];
#pragma unroll
            for (int i = 0; i < 4; i++)
                qv[i] = *(const float4*)&Qs[(ty * 4 + i) * PQ + d];
#pragma unroll
            for (int jj = 0; jj < 4; jj++)
                kv[jj] = *(const float4*)&Ks[(tx + 16 * jj) * PQ + d];
#pragma unroll
            for (int i = 0; i < 4; i++)
#pragma unroll
                for (int jj = 0; jj < 4; jj++) {
                    s[i][jj] = fmaf(qv[i].x, kv[jj].x, s[i][jj]);
                    s[i][jj] = fmaf(qv[i].y, kv[jj].y, s[i][jj]);
                    s[i][jj] = fmaf(qv[i].z, kv[jj].z, s[i][jj]);
                    s[i][jj] = fmaf(qv[i].w, kv[jj].w, s[i][jj]);
                }
        }

#pragma unroll
        for (int i = 0; i < 4; i++) {
            int qg = q0 + ty * 4 + i;
#pragma unroll
            for (int jj = 0; jj < 4; jj++) {
                int jg = jt * BKV + tx + 16 * jj;
                s[i][jj] = (jg > qg) ? -1e30f : s[i][jj] * SCALE_;
            }
        }

#pragma unroll
        for (int i = 0; i < 4; i++) {
            float mx = fmaxf(fmaxf(s[i][0], s[i][1]), fmaxf(s[i][2], s[i][3]));
#pragma unroll
            for (int o = 8; o >= 1; o >>= 1)
                mx = fmaxf(mx, __shfl_xor_sync(0xffffffffu, mx, o));
            float mnew = fmaxf(m_i[i], mx);
            float alpha = __expf(m_i[i] - mnew);
            float rsum = 0.0f;
#pragma unroll
            for (int jj = 0; jj < 4; jj++) {
                float p = __expf(s[i][jj] - mnew);
                rsum += p;
                Ps[(ty * 4 + i) * BKV + tx + 16 * jj] = p;
            }
#pragma unroll
            for (int o = 8; o >= 1; o >>= 1)
                rsum += __shfl_xor_sync(0xffffffffu, rsum, o);
            l_i[i] = l_i[i] * alpha + rsum;
            m_i[i] = mnew;
#pragma unroll
            for (int cc = 0; cc < 5; cc++) acc[i][cc] *= alpha;
        }
        __syncthreads();

        for (int j = 0; j < BKV; j += 4) {
            float4 pv[4];
#pragma unroll
            for (int i = 0; i < 4; i++)
                pv[i] = *(const float4*)&Ps[(ty * 4 + i) * BKV + j];
#pragma unroll
            for (int jj2 = 0; jj2 < 4; jj2++) {
                float vv[5];
#pragma unroll
                for (int cc = 0; cc < 5; cc++)
                    vv[cc] = Vs[(j + jj2) * D_ + tx + 16 * cc];
#pragma unroll
                for (int i = 0; i < 4; i++) {
                    float p = (jj2 == 0) ? pv[i].x : (jj2 == 1) ? pv[i].y
                             : (jj2 == 2) ? pv[i].z : pv[i].w;
#pragma unroll
                    for (int cc = 0; cc < 5; cc++)
                        acc[i][cc] = fmaf(p, vv[cc], acc[i][cc]);
                }
            }
        }
        __syncthreads();
    }

#pragma unroll
    for (int i = 0; i < 4; i++) {
        float inv = 1.0f / l_i[i];
        float* op = outp + (size_t)(b * S_ + q0 + ty * 4 + i) * HID_ + h * D_;
#pragma unroll
        for (int cc = 0; cc < 5; cc++)
            op[tx + 16 * cc] = tf32r(acc[i][cc] * inv);
    }
}

// ---------------------------------------------------------------------------
// kernel_launch
// ---------------------------------------------------------------------------
extern "C" void kernel_launch(void* const* d_in, const int* in_sizes, int n_in,
                              void* d_out, int out_size)
{
    const float* hidden  = (const float*)d_in[0];
    const float* cosp    = (const float*)d_in[1];
    const float* sinp    = (const float*)d_in[2];
    const float* w_qkv   = (const float*)d_in[3];
    const float* b_qkv   = (const float*)d_in[4];
    const float* w_dense = (const float*)d_in[5];
    const float* b_dense = (const float*)d_in[6];
    float* outp = (float*)d_out;

    float *qkv, *attn, *hidT, *wqkvT, *wdT;
    cudaGetSymbolAddress((void**)&qkv,   g_qkv);
    cudaGetSymbolAddress((void**)&attn,  g_attn);
    cudaGetSymbolAddress((void**)&hidT,  g_hidT);
    cudaGetSymbolAddress((void**)&wqkvT, g_wqkvT);
    cudaGetSymbolAddress((void**)&wdT,   g_wdT);

    cudaFuncSetAttribute(attn_kernel,
                         cudaFuncAttributeMaxDynamicSharedMemorySize, ATTN_SMEM_BYTES);

    // 0) round inputs to tf32 (RNA, unbiased)
    cvt_tf32_kernel<<<(T_ * HID_ / 4 + 255) / 256, 256>>>(
        (const float4*)hidden, (float4*)hidT, T_ * HID_ / 4);
    cvt_tf32_kernel<<<((size_t)QKV_N * HID_ / 4 + 255) / 256, 256>>>(
        (const float4*)w_qkv, (float4*)wqkvT, QKV_N * HID_ / 4);
    cvt_tf32_kernel<<<((size_t)HID_ * HID_ / 4 + 255) / 256, 256>>>(
        (const float4*)w_dense, (float4*)wdT, HID_ * HID_ / 4);

    // 1) QKV GEMM (mma.sync tf32) + bias
    {
        dim3 grid(QKV_N / GN, T_ / GM);   // (60, 32)
        mma_gemm<<<grid, 256>>>(hidT, wqkvT, b_qkv, qkv, T_, QKV_N, HID_);
    }

    // 2) partial RoPE
    {
        int total = 2 * T_ * H_ * HALF_;
        rope_kernel<<<total / 256, 256>>>(qkv, cosp, sinp);
    }

    // 3) causal flash attention (epilogue rounds to tf32)
    {
        dim3 grid(S_ / BQ, B_ * H_);
        attn_kernel<<<grid, 256, ATTN_SMEM_BYTES>>>(qkv, attn);
    }

    // 4) dense GEMM (mma.sync tf32) + bias -> final output
    {
        dim3 grid(HID_ / GN, T_ / GM);    // (20, 32)
        mma_gemm<<<grid, 256>>>(attn, wdT, b_dense, outp, T_, HID_, HID_);
    }
}